// round 2
// baseline (speedup 1.0000x reference)
#include <cuda_runtime.h>
#include <math.h>

#define N_NAMED 8000
#define ANON_E 192
#define N_TOTAL 8192
#define DIM 128
#define BLOCKS 128
#define THREADS 256                       // 8 warps
#define WARPS (THREADS / 32)
#define ROWS_PER_BLOCK (N_TOTAL / BLOCKS)     // 64
#define ROWS_PER_WARP (ROWS_PER_BLOCK / WARPS) // 8

// Cross-block scratch (no cudaMalloc allowed)
__device__ float    g_pmax[BLOCKS];
__device__ unsigned g_bar  = 0;
__device__ unsigned g_bar2 = 0;

__global__ void __launch_bounds__(THREADS)
falcon_fused(const float* __restrict__ anon,
             const float* __restrict__ etab,
             const float* __restrict__ ctab,
             const float* __restrict__ rtab,
             const float* __restrict__ w,    // [256]: w_l | w_r
             const float* __restrict__ bptr,
             const int*   __restrict__ cid,
             const int*   __restrict__ rid,
             float*       __restrict__ out)
{
    __shared__ float s_w[2 * DIM];
    __shared__ float s_dl[ROWS_PER_BLOCK];
    __shared__ float s_max[WARPS];
    __shared__ float s_scal[3];            // cmax, c_dot, r_dot

    const int tid  = threadIdx.x;
    const int warp = tid >> 5;
    const int lane = tid & 31;
    const int bid  = blockIdx.x;

    s_w[tid] = w[tid];
    __syncthreads();

    const float4 wl = reinterpret_cast<const float4*>(s_w)[lane];
    const float4 wr = reinterpret_cast<const float4*>(s_w + DIM)[lane];

    // ---- Phase 1: both GEMV dots for this block's 64 rows ----
    const int base = bid * ROWS_PER_BLOCK + warp * ROWS_PER_WARP;

    // batch the 8 row loads first (MLP=8)
    float4 v[ROWS_PER_WARP];
#pragma unroll
    for (int k = 0; k < ROWS_PER_WARP; ++k) {
        const int r = base + k;
        const float* e = (r < N_NAMED)
                           ? (etab + (size_t)r * DIM)
                           : (anon + (size_t)(r - N_NAMED) * DIM);
        v[k] = reinterpret_cast<const float4*>(e)[lane];
    }

    float lmax = -3.4e38f;
#pragma unroll
    for (int k = 0; k < ROWS_PER_WARP; ++k) {
        float dl = v[k].x * wl.x + v[k].y * wl.y + v[k].z * wl.z + v[k].w * wl.w;
        float dr = v[k].x * wr.x + v[k].y * wr.y + v[k].z * wr.z + v[k].w * wr.w;
#pragma unroll
        for (int o = 16; o > 0; o >>= 1) {
            dl += __shfl_down_sync(0xffffffffu, dl, o);
            dr += __shfl_down_sync(0xffffffffu, dr, o);
        }
        if (lane == 0) {
            s_dl[warp * ROWS_PER_WARP + k] = dl;
            lmax = fmaxf(lmax, dr);
        }
    }
    if (lane == 0) s_max[warp] = lmax;
    __syncthreads();

    if (tid == 0) {
        float m = s_max[0];
#pragma unroll
        for (int i = 1; i < WARPS; ++i) m = fmaxf(m, s_max[i]);
        g_pmax[bid] = m;
        __threadfence();
        atomicAdd(&g_bar, 1u);
        // spin until every block has published its partial max
        while (*(volatile unsigned*)&g_bar < BLOCKS) { }
    }
    __syncthreads();
    __threadfence();   // acquire: make all g_pmax writes visible

    // ---- Phase 2: scalars (redundant per block; tiny, L2-resident) ----
    if (tid < 32) {
        float m = fmaxf(fmaxf(g_pmax[lane],      g_pmax[lane + 32]),
                        fmaxf(g_pmax[lane + 64], g_pmax[lane + 96]));

        const float* ce = ctab + (size_t)(*cid) * DIM;
        const float* re = rtab + (size_t)(*rid) * DIM;
        float cd = 0.f, rd = 0.f;
#pragma unroll
        for (int kk = 0; kk < 4; ++kk) {
            const float wlv = s_w[lane * 4 + kk];   // w_l
            cd += __ldg(&ce[lane * 4 + kk]) * wlv;
            rd += __ldg(&re[lane * 4 + kk]) * wlv;
        }
#pragma unroll
        for (int o = 16; o > 0; o >>= 1) {
            m  = fmaxf(m, __shfl_down_sync(0xffffffffu, m, o));
            cd += __shfl_down_sync(0xffffffffu, cd, o);
            rd += __shfl_down_sync(0xffffffffu, rd, o);
        }
        if (lane == 0) { s_scal[0] = m; s_scal[1] = cd; s_scal[2] = rd; }
    }
    __syncthreads();

    // ---- Phase 3: outputs for this block's rows ----
    // Exact collapse: both sigmoid factors strictly increase in col_j,
    // so argmax_j is at col_max for every i.
    if (tid < ROWS_PER_BLOCK) {
        const float cmax = s_scal[0];
        const float b    = *bptr;
        const float cfs  = 1.f / (1.f + __expf(-(s_scal[1] + cmax + b)));
        const float rfs  = 1.f / (1.f + __expf(-(s_dl[tid] + s_scal[2] + cmax + b)));
        out[bid * ROWS_PER_BLOCK + tid] = rfs * cfs;
    }

    // ---- Reset barrier state for the next graph replay ----
    __syncthreads();
    if (tid == 0) {
        const unsigned t = atomicAdd(&g_bar2, 1u);
        if (t == BLOCKS - 1) {            // last block out resets both counters
            atomicExch(&g_bar,  0u);
            atomicExch(&g_bar2, 0u);
        }
    }
}

extern "C" void kernel_launch(void* const* d_in, const int* in_sizes, int n_in,
                              void* d_out, int out_size) {
    const float* anon = (const float*)d_in[0];   // [192,128]
    const float* etab = (const float*)d_in[1];   // [8000,128]
    const float* ctab = (const float*)d_in[2];   // [100,128]
    const float* rtab = (const float*)d_in[3];   // [50,128]
    const float* w    = (const float*)d_in[4];   // [1,256]
    const float* bb   = (const float*)d_in[5];   // [1]
    const int*   cid  = (const int*)d_in[6];
    const int*   rid  = (const int*)d_in[7];

    falcon_fused<<<BLOCKS, THREADS>>>(anon, etab, ctab, rtab, w, bb, cid, rid,
                                      (float*)d_out);
}

// round 3
// speedup vs baseline: 1.5055x; 1.5055x over previous
#include <cuda_runtime.h>
#include <math.h>

#define N_NAMED 8000
#define N_TOTAL 8192
#define DIM 128
#define BLOCKS 64
#define THREADS 256
#define WARPS 8
#define RPB (N_TOTAL / BLOCKS)   // 128 rows per block
#define RPW (RPB / WARPS)        // 16 rows per warp

// Cross-block scratch (no cudaMalloc allowed)
__device__ float    g_pmax[BLOCKS];
__device__ unsigned g_bar = 0;   // monotone ticket barrier — NEVER reset

__device__ __forceinline__ unsigned ld_acq(const unsigned* p) {
    unsigned v;
    asm volatile("ld.acquire.gpu.global.u32 %0, [%1];" : "=r"(v) : "l"(p) : "memory");
    return v;
}
__device__ __forceinline__ unsigned arrive_release(unsigned* p) {
    unsigned old;
    asm volatile("atom.release.gpu.global.add.u32 %0, [%1], 1;"
                 : "=r"(old) : "l"(p) : "memory");
    return old;
}

__global__ void __launch_bounds__(THREADS)
falcon_fused(const float* __restrict__ anon,
             const float* __restrict__ etab,
             const float* __restrict__ ctab,
             const float* __restrict__ rtab,
             const float* __restrict__ w,    // [256]: w_l | w_r
             const float* __restrict__ bptr,
             const int*   __restrict__ cid,
             const int*   __restrict__ rid,
             float*       __restrict__ out)
{
    __shared__ float s_w[2 * DIM];
    __shared__ float s_dl[RPB];
    __shared__ float s_max[WARPS];
    __shared__ float s_scal[4];        // cmax, c_dot, r_dot, b

    const int tid  = threadIdx.x;
    const int warp = tid >> 5;
    const int lane = tid & 31;
    const int bid  = blockIdx.x;

    s_w[tid] = w[tid];
    __syncthreads();

    const float4 wl = reinterpret_cast<const float4*>(s_w)[lane];
    const float4 wr = reinterpret_cast<const float4*>(s_w + DIM)[lane];

    // ---- batched row loads: 16 LDG.128 in flight per lane ----
    const int base = bid * RPB + warp * RPW;
    float4 v[RPW];
#pragma unroll
    for (int k = 0; k < RPW; ++k) {
        const int r = base + k;
        const float* e = (r < N_NAMED)
                           ? (etab + (size_t)r * DIM)
                           : (anon + (size_t)(r - N_NAMED) * DIM);
        v[k] = reinterpret_cast<const float4*>(e)[lane];
    }

    // ---- Phase A: w_r dots only -> block max -> publish ASAP ----
    float lmax = -3.4e38f;
#pragma unroll
    for (int k = 0; k < RPW; ++k) {
        float dr = v[k].x * wr.x + v[k].y * wr.y + v[k].z * wr.z + v[k].w * wr.w;
#pragma unroll
        for (int o = 16; o > 0; o >>= 1)
            dr += __shfl_xor_sync(0xffffffffu, dr, o);   // butterfly: sum in all lanes
        lmax = fmaxf(lmax, dr);
    }
    if (lane == 0) s_max[warp] = lmax;
    __syncthreads();

    unsigned target = 0;
    if (tid == 0) {
        float m = s_max[0];
#pragma unroll
        for (int i = 1; i < WARPS; ++i) m = fmaxf(m, s_max[i]);
        g_pmax[bid] = m;                       // ordered by release below
        const unsigned t = arrive_release(&g_bar);
        target = (t / BLOCKS + 1u) * BLOCKS;   // this replay's release count
    }

    // ---- Phase B (overlaps barrier propagation): w_l dots ----
#pragma unroll
    for (int k = 0; k < RPW; ++k) {
        float dl = v[k].x * wl.x + v[k].y * wl.y + v[k].z * wl.z + v[k].w * wl.w;
#pragma unroll
        for (int o = 16; o > 0; o >>= 1)
            dl += __shfl_xor_sync(0xffffffffu, dl, o);
        if (lane == 0) s_dl[warp * RPW + k] = dl;
    }

    // ---- Phase C (also overlaps barrier): scalar dots in warp 1 ----
    if (warp == 1) {
        const float* ce = ctab + (size_t)__ldg(cid) * DIM;
        const float* re = rtab + (size_t)__ldg(rid) * DIM;
        float cd = 0.f, rd = 0.f;
#pragma unroll
        for (int kk = 0; kk < 4; ++kk) {
            const float wlv = s_w[lane * 4 + kk];          // w_l
            cd += __ldg(&ce[lane * 4 + kk]) * wlv;
            rd += __ldg(&re[lane * 4 + kk]) * wlv;
        }
#pragma unroll
        for (int o = 16; o > 0; o >>= 1) {
            cd += __shfl_xor_sync(0xffffffffu, cd, o);
            rd += __shfl_xor_sync(0xffffffffu, rd, o);
        }
        if (lane == 0) {
            s_scal[1] = cd;
            s_scal[2] = rd;
            s_scal[3] = __ldg(bptr);
        }
    }

    // ---- Spin (thread 0 only; others park at the barrier) ----
    if (tid == 0) {
        while (ld_acq(&g_bar) < target) { }
    }
    __syncthreads();

    // ---- global max of 64 per-block partials (L2-hot, 256 B) ----
    if (warp == 0) {
        float m = fmaxf(g_pmax[lane], g_pmax[lane + 32]);
#pragma unroll
        for (int o = 16; o > 0; o >>= 1)
            m = fmaxf(m, __shfl_xor_sync(0xffffffffu, m, o));
        if (lane == 0) s_scal[0] = m;
    }
    __syncthreads();

    // ---- outputs: exact collapse (both sigmoids strictly increase in col_j,
    //      so argmax_j sits at col_max for every i) ----
    if (tid < RPB) {
        const float cmax = s_scal[0];
        const float b    = s_scal[3];
        const float cfs  = 1.f / (1.f + __expf(-(s_scal[1] + cmax + b)));
        const float rfs  = 1.f / (1.f + __expf(-(s_dl[tid] + s_scal[2] + cmax + b)));
        out[bid * RPB + tid] = rfs * cfs;
    }
}

extern "C" void kernel_launch(void* const* d_in, const int* in_sizes, int n_in,
                              void* d_out, int out_size) {
    const float* anon = (const float*)d_in[0];   // [192,128]
    const float* etab = (const float*)d_in[1];   // [8000,128]
    const float* ctab = (const float*)d_in[2];   // [100,128]
    const float* rtab = (const float*)d_in[3];   // [50,128]
    const float* w    = (const float*)d_in[4];   // [1,256]
    const float* bb   = (const float*)d_in[5];   // [1]
    const int*   cid  = (const int*)d_in[6];
    const int*   rid  = (const int*)d_in[7];

    falcon_fused<<<BLOCKS, THREADS>>>(anon, etab, ctab, rtab, w, bb, cid, rid,
                                      (float*)d_out);
}

// round 4
// speedup vs baseline: 1.5396x; 1.0226x over previous
#include <cuda_runtime.h>
#include <math.h>

#define N_NAMED 8000
#define N_TOTAL 8192
#define DIM 128
#define BLOCKS 128
#define THREADS 256
#define WARPS 8
#define RPB (N_TOTAL / BLOCKS)   // 64 rows per block
#define RPW (RPB / WARPS)        // 8 rows per warp

// Cross-block scratch (no cudaMalloc allowed)
__device__ float    g_pmax[BLOCKS];
__device__ unsigned g_bar = 0;   // monotone ticket barrier — NEVER reset

__device__ __forceinline__ unsigned ld_acq(const unsigned* p) {
    unsigned v;
    asm volatile("ld.acquire.gpu.global.u32 %0, [%1];" : "=r"(v) : "l"(p) : "memory");
    return v;
}
__device__ __forceinline__ unsigned arrive_release(unsigned* p) {
    unsigned old;
    asm volatile("atom.release.gpu.global.add.u32 %0, [%1], 1;"
                 : "=r"(old) : "l"(p) : "memory");
    return old;
}

__global__ void __launch_bounds__(THREADS)
falcon_fused(const float* __restrict__ anon,
             const float* __restrict__ etab,
             const float* __restrict__ ctab,
             const float* __restrict__ rtab,
             const float* __restrict__ w,    // [256]: w_l | w_r
             const float* __restrict__ bptr,
             const int*   __restrict__ cid,
             const int*   __restrict__ rid,
             float*       __restrict__ out)
{
    __shared__ float s_w[2 * DIM];
    __shared__ float s_dl[RPB];
    __shared__ float s_max[WARPS];
    __shared__ float s_scal[4];        // cmax, c_dot, r_dot, b

    const int tid  = threadIdx.x;
    const int warp = tid >> 5;
    const int lane = tid & 31;
    const int bid  = blockIdx.x;

    s_w[tid] = w[tid];
    __syncthreads();

    const float4 wl = reinterpret_cast<const float4*>(s_w)[lane];
    const float4 wr = reinterpret_cast<const float4*>(s_w + DIM)[lane];

    // ---- batched row loads: 8 LDG.128 in flight per lane ----
    const int base = bid * RPB + warp * RPW;
    float4 v[RPW];
#pragma unroll
    for (int k = 0; k < RPW; ++k) {
        const int r = base + k;
        const float* e = (r < N_NAMED)
                           ? (etab + (size_t)r * DIM)
                           : (anon + (size_t)(r - N_NAMED) * DIM);
        v[k] = reinterpret_cast<const float4*>(e)[lane];
    }

    // ---- Phase A: w_r dots -> block max -> publish ASAP ----
    float lmax = -3.4e38f;
#pragma unroll
    for (int k = 0; k < RPW; ++k) {
        float dr = v[k].x * wr.x + v[k].y * wr.y + v[k].z * wr.z + v[k].w * wr.w;
#pragma unroll
        for (int o = 16; o > 0; o >>= 1)
            dr += __shfl_xor_sync(0xffffffffu, dr, o);
        lmax = fmaxf(lmax, dr);
    }
    if (lane == 0) s_max[warp] = lmax;
    __syncthreads();

    unsigned target = 0;
    if (tid == 0) {
        float m = s_max[0];
#pragma unroll
        for (int i = 1; i < WARPS; ++i) m = fmaxf(m, s_max[i]);
        g_pmax[bid] = m;                       // ordered by release below
        const unsigned t = arrive_release(&g_bar);
        target = (t / BLOCKS + 1u) * BLOCKS;   // this replay's release count
    }

    // ---- Phase B (overlaps barrier propagation): w_l dots ----
#pragma unroll
    for (int k = 0; k < RPW; ++k) {
        float dl = v[k].x * wl.x + v[k].y * wl.y + v[k].z * wl.z + v[k].w * wl.w;
#pragma unroll
        for (int o = 16; o > 0; o >>= 1)
            dl += __shfl_xor_sync(0xffffffffu, dl, o);
        if (lane == 0) s_dl[warp * RPW + k] = dl;
    }

    // ---- Phase C (also overlaps barrier): scalar dots in warp 1 ----
    if (warp == 1) {
        const float* ce = ctab + (size_t)__ldg(cid) * DIM;
        const float* re = rtab + (size_t)__ldg(rid) * DIM;
        float cd = 0.f, rd = 0.f;
#pragma unroll
        for (int kk = 0; kk < 4; ++kk) {
            const float wlv = s_w[lane * 4 + kk];          // w_l
            cd += __ldg(&ce[lane * 4 + kk]) * wlv;
            rd += __ldg(&re[lane * 4 + kk]) * wlv;
        }
#pragma unroll
        for (int o = 16; o > 0; o >>= 1) {
            cd += __shfl_xor_sync(0xffffffffu, cd, o);
            rd += __shfl_xor_sync(0xffffffffu, rd, o);
        }
        if (lane == 0) {
            s_scal[1] = cd;
            s_scal[2] = rd;
            s_scal[3] = __ldg(bptr);
        }
    }

    // ---- Spin (thread 0 only; others park at the block barrier) ----
    if (tid == 0) {
        while (ld_acq(&g_bar) < target) { }
    }
    __syncthreads();

    // ---- global max over 128 per-block partials (L2-hot, 512 B) ----
    if (warp == 0) {
        float m = fmaxf(fmaxf(g_pmax[lane],      g_pmax[lane + 32]),
                        fmaxf(g_pmax[lane + 64], g_pmax[lane + 96]));
#pragma unroll
        for (int o = 16; o > 0; o >>= 1)
            m = fmaxf(m, __shfl_xor_sync(0xffffffffu, m, o));
        if (lane == 0) s_scal[0] = m;
    }
    __syncthreads();

    // ---- outputs: exact collapse (both sigmoids strictly increase in col_j,
    //      so argmax_j sits at col_max for every i) ----
    if (tid < RPB) {
        const float cmax = s_scal[0];
        const float b    = s_scal[3];
        const float cfs  = 1.f / (1.f + __expf(-(s_scal[1] + cmax + b)));
        const float rfs  = 1.f / (1.f + __expf(-(s_dl[tid] + s_scal[2] + cmax + b)));
        out[bid * RPB + tid] = rfs * cfs;
    }
}

extern "C" void kernel_launch(void* const* d_in, const int* in_sizes, int n_in,
                              void* d_out, int out_size) {
    const float* anon = (const float*)d_in[0];   // [192,128]
    const float* etab = (const float*)d_in[1];   // [8000,128]
    const float* ctab = (const float*)d_in[2];   // [100,128]
    const float* rtab = (const float*)d_in[3];   // [50,128]
    const float* w    = (const float*)d_in[4];   // [1,256]
    const float* bb   = (const float*)d_in[5];   // [1]
    const int*   cid  = (const int*)d_in[6];
    const int*   rid  = (const int*)d_in[7];

    falcon_fused<<<BLOCKS, THREADS>>>(anon, etab, ctab, rtab, w, bb, cid, rid,
                                      (float*)d_out);
}